// round 16
// baseline (speedup 1.0000x reference)
#include <cuda_runtime.h>
#include <cstdint>

#define B_ 64
#define T_ 2048
#define I_ 512
#define H_ 1024
#define MTOT (B_ * T_)
#define BSTRIDE ((size_t)T_ * H_)   // stride between batch rows in out
#define NBLK 128                    // persistent grid: 16 n-tiles x 8 k-slabs
#define KP2 132                     // rec padded k-row (128+4 fp32 words)
#define PKP2 36                     // proj padded k-row (32+4 words)

__device__ unsigned g_bar;          // grid-barrier arrival counter

// ---------------------------------------------------------------------------
// helpers (validated in R10)
// ---------------------------------------------------------------------------
__device__ __forceinline__ uint32_t f2tf32(float x) {
    uint32_t u;
    asm("cvt.rna.tf32.f32 %0, %1;" : "=r"(u) : "f"(x));
    return u;
}
__device__ __forceinline__ void mma_tf32(float* d, const uint32_t* a, const uint32_t* b) {
    asm volatile(
        "mma.sync.aligned.m16n8k8.row.col.f32.tf32.tf32.f32 "
        "{%0,%1,%2,%3}, {%4,%5,%6,%7}, {%8,%9}, {%0,%1,%2,%3};"
        : "+f"(d[0]), "+f"(d[1]), "+f"(d[2]), "+f"(d[3])
        : "r"(a[0]), "r"(a[1]), "r"(a[2]), "r"(a[3]), "r"(b[0]), "r"(b[1]));
}
// 2-way tf32 split: x = hi + lo + delta, |delta| <= 2^-24 |x|.
__device__ __forceinline__ void split4(float* hi, float* lo, float4 v) {
    float f[4] = {v.x, v.y, v.z, v.w};
    float h[4], l[4];
#pragma unroll
    for (int i = 0; i < 4; i++) {
        h[i] = __uint_as_float(f2tf32(f[i]));
        l[i] = __uint_as_float(f2tf32(f[i] - h[i]));
    }
    *(float4*)hi = make_float4(h[0], h[1], h[2], h[3]);
    *(float4*)lo = make_float4(l[0], l[1], l[2], l[3]);
}

// ---------------------------------------------------------------------------
// init: reset grid barrier (must run every replay)
// ---------------------------------------------------------------------------
__global__ void init_kernel() { g_bar = 0u; }

// ---------------------------------------------------------------------------
// Projection (TF32 MMA, 2-way split, 4 terms) — R10-VALIDATED, byte-identical.
// out = x@W^T + Ub + b. M=131072, N=1024, K=512. 128x128 tile, bk=32, 8 warps.
// ---------------------------------------------------------------------------
__global__ __launch_bounds__(256) void proj_tf32_kernel(
    const float* __restrict__ x, const float* __restrict__ W,
    const float* __restrict__ Ub, const float* __restrict__ bvec,
    float* __restrict__ out)
{
    extern __shared__ float psm[];
    float* Axh = psm;                 // [128][PKP2] each
    float* Axl = Axh + 128 * PKP2;
    float* Bwh = Axl + 128 * PKP2;
    float* Bwl = Bwh + 128 * PKP2;

    const int tid  = threadIdx.x;
    const int lane = tid & 31;
    const int g    = lane >> 2;       // groupID 0..7
    const int tg   = lane & 3;        // thread-in-group 0..3
    const int wid  = tid >> 5;
    const int m0 = blockIdx.y * 128;
    const int n0 = blockIdx.x * 128;
    const int wm = (wid & 3) * 32;    // warp m offset (32 rows)
    const int wn = (wid >> 2) * 64;   // warp n offset (64 cols)

    float D[2][8][4];
#pragma unroll
    for (int i = 0; i < 2; i++)
#pragma unroll
        for (int j = 0; j < 8; j++)
#pragma unroll
            for (int k = 0; k < 4; k++) D[i][j][k] = 0.f;

    for (int kb = 0; kb < I_; kb += 32) {
        __syncthreads();
#pragma unroll
        for (int l = 0; l < 4; l++) {
            int idx = tid + l * 256;     // 0..1023
            int row = idx >> 3;          // 0..127
            int c4  = (idx & 7) << 2;    // 0..28
            float4 xv = *(const float4*)(x + (size_t)(m0 + row) * I_ + kb + c4);
            split4(Axh + row * PKP2 + c4, Axl + row * PKP2 + c4, xv);
            float4 wv = *(const float4*)(W + (size_t)(n0 + row) * I_ + kb + c4);
            split4(Bwh + row * PKP2 + c4, Bwl + row * PKP2 + c4, wv);
        }
        __syncthreads();

#pragma unroll
        for (int kc = 0; kc < 4; kc++) {
            const int col = kc * 8 + tg;
            uint32_t ah[2][4], al[2][4];
#pragma unroll
            for (int mt = 0; mt < 2; mt++) {
                int r = wm + mt * 16 + g;
                ah[mt][0] = __float_as_uint(Axh[r * PKP2 + col]);
                ah[mt][1] = __float_as_uint(Axh[(r + 8) * PKP2 + col]);
                ah[mt][2] = __float_as_uint(Axh[r * PKP2 + col + 4]);
                ah[mt][3] = __float_as_uint(Axh[(r + 8) * PKP2 + col + 4]);
                al[mt][0] = __float_as_uint(Axl[r * PKP2 + col]);
                al[mt][1] = __float_as_uint(Axl[(r + 8) * PKP2 + col]);
                al[mt][2] = __float_as_uint(Axl[r * PKP2 + col + 4]);
                al[mt][3] = __float_as_uint(Axl[(r + 8) * PKP2 + col + 4]);
            }
#pragma unroll
            for (int nt = 0; nt < 8; nt++) {
                int n = wn + nt * 8 + g;
                uint32_t bh[2], bl[2];
                bh[0] = __float_as_uint(Bwh[n * PKP2 + col]);
                bh[1] = __float_as_uint(Bwh[n * PKP2 + col + 4]);
                bl[0] = __float_as_uint(Bwl[n * PKP2 + col]);
                bl[1] = __float_as_uint(Bwl[n * PKP2 + col + 4]);
#pragma unroll
                for (int mt = 0; mt < 2; mt++) {
                    mma_tf32(D[mt][nt], ah[mt], bh);   // hh
                    mma_tf32(D[mt][nt], ah[mt], bl);   // hl
                    mma_tf32(D[mt][nt], al[mt], bh);   // lh
                    mma_tf32(D[mt][nt], al[mt], bl);   // ll
                }
            }
        }
    }

#pragma unroll
    for (int nt = 0; nt < 8; nt++) {
        int n = n0 + wn + nt * 8 + tg * 2;
        float ub0 = Ub[n]     + bvec[n];
        float ub1 = Ub[n + 1] + bvec[n + 1];
#pragma unroll
        for (int mt = 0; mt < 2; mt++) {
            int m = m0 + wm + mt * 16 + g;
            float2 v0 = make_float2(D[mt][nt][0] + ub0, D[mt][nt][1] + ub1);
            float2 v1 = make_float2(D[mt][nt][2] + ub0, D[mt][nt][3] + ub1);
            *(float2*)(out + (size_t)m * H_ + n)       = v0;
            *(float2*)(out + (size_t)(m + 8) * H_ + n) = v1;
        }
    }
}

// ---------------------------------------------------------------------------
// Persistent recurrence — TF32 MMA, 4 terms, SHORT ACCUMULATOR CHAINS.
// The hypothesized defect: MMA fp32 accumulator alignment adds truncate toward
// zero -> coherent shrinkage ~ chain_length x 2^-26 per step, compounding
// linearly over 2047 steps (fits R5..R11 at ~1.7e-3).
// Fix: hh (large magnitude) chains are LENGTH 2, partial sums combined with
// IEEE-RN register FADDs (unbiased). Small terms (hl, lh, ll ~ 2^-12|y|) stay
// in one long chain where the bias is scaled down by their magnitude.
//   out[b][t][n] += sum_k out[b][t-1][k] * Uw[n][k]
// Layout / fragments / staging / barrier byte-identical to R11.
// ---------------------------------------------------------------------------
__global__ __launch_bounds__(256) void rnn_persistent_kernel(
    float* __restrict__ out, const float* __restrict__ Uw)
{
    extern __shared__ float sm[];
    float* Uh = sm;                  // [64][KP2] each
    float* Ul = Uh + 64 * KP2;
    float* Sh = Ul + 64 * KP2;
    float* Sl = Sh + 64 * KP2;

    const int tid  = threadIdx.x;
    const int lane = tid & 31;
    const int g    = lane >> 2;       // groupID 0..7
    const int tg   = lane & 3;        // thread-in-group 0..3
    const int wid  = tid >> 5;
    const int bid  = blockIdx.x;
    const int n0 = (bid & 15) * 64;
    const int k0 = (bid >> 4) * 128;
    const int wm = (wid & 3) * 16;    // batch-row tile (16 of 64)
    const int wn = (wid >> 2) * 32;   // n offset within 64 (2 halves)

    // Preload Uw slab once: rows n (64), cols k (128), split hi/lo
#pragma unroll
    for (int l = 0; l < 8; l++) {
        int idx = tid + l * 256;     // 0..2047
        int r   = idx >> 5;          // 0..63  (n)
        int c4  = (idx & 31) << 2;   // 0..124 (k)
        float4 v = *(const float4*)(Uw + (size_t)(n0 + r) * H_ + k0 + c4);
        split4(Uh + r * KP2 + c4, Ul + r * KP2 + c4, v);
    }
    __syncthreads();

    for (int t = 1; t < T_; t++) {
        // Stage prev state slab [64 b][128 k] fp32 -> hi/lo tf32
        const float* prev = out + (size_t)(t - 1) * H_ + k0;
#pragma unroll
        for (int l = 0; l < 8; l++) {
            int idx = tid + l * 256;
            int r   = idx >> 5;          // batch row
            int c4  = (idx & 31) << 2;
            float4 v = *(const float4*)(prev + (size_t)r * BSTRIDE + c4);
            split4(Sh + r * KP2 + c4, Sl + r * KP2 + c4, v);
        }
        __syncthreads();

        float Dsum[4][4];    // RN-combined hh partials
        float Dhh[4][4];     // current length-2 hh chain
        float Drest[4][4];   // hl + lh + ll (small magnitude, one long chain)
#pragma unroll
        for (int i = 0; i < 4; i++)
#pragma unroll
            for (int j = 0; j < 4; j++) { Dsum[i][j] = 0.f; Drest[i][j] = 0.f; }

#pragma unroll
        for (int kc = 0; kc < 16; kc++) {       // 16 x k8 chunks
            const int col = kc * 8 + tg;
            uint32_t ah[4], al[4];
            {
                int r = wm + g;
                ah[0] = __float_as_uint(Sh[r * KP2 + col]);
                ah[1] = __float_as_uint(Sh[(r + 8) * KP2 + col]);
                ah[2] = __float_as_uint(Sh[r * KP2 + col + 4]);
                ah[3] = __float_as_uint(Sh[(r + 8) * KP2 + col + 4]);
                al[0] = __float_as_uint(Sl[r * KP2 + col]);
                al[1] = __float_as_uint(Sl[(r + 8) * KP2 + col]);
                al[2] = __float_as_uint(Sl[r * KP2 + col + 4]);
                al[3] = __float_as_uint(Sl[(r + 8) * KP2 + col + 4]);
            }
#pragma unroll
            for (int nt = 0; nt < 4; nt++) {
                int n = wn + nt * 8 + g;
                uint32_t bh[2], bl[2];
                bh[0] = __float_as_uint(Uh[n * KP2 + col]);
                bh[1] = __float_as_uint(Uh[n * KP2 + col + 4]);
                bl[0] = __float_as_uint(Ul[n * KP2 + col]);
                bl[1] = __float_as_uint(Ul[n * KP2 + col + 4]);

                if ((kc & 1) == 0) {   // start a fresh length-2 hh chain
#pragma unroll
                    for (int j = 0; j < 4; j++) Dhh[nt][j] = 0.f;
                }
                mma_tf32(Dhh[nt],   ah, bh);   // hh (short chain)
                mma_tf32(Drest[nt], ah, bl);   // hl (long chain, tiny magnitude)
                mma_tf32(Drest[nt], al, bh);   // lh
                mma_tf32(Drest[nt], al, bl);   // ll
                if ((kc & 1) == 1) {   // close chain: RN-add into Dsum
#pragma unroll
                    for (int j = 0; j < 4; j++) Dsum[nt][j] += Dhh[nt][j];
                }
            }
        }

        // Merge partials onto wx at out[:, t, :]
#pragma unroll
        for (int nt = 0; nt < 4; nt++) {
            float d0 = Dsum[nt][0] + Drest[nt][0];
            float d1 = Dsum[nt][1] + Drest[nt][1];
            float d2 = Dsum[nt][2] + Drest[nt][2];
            float d3 = Dsum[nt][3] + Drest[nt][3];
            int n  = n0 + wn + nt * 8 + tg * 2;
            int br = wm + g;
            float* dst0 = out + (size_t)br * BSTRIDE + (size_t)t * H_ + n;
            asm volatile("red.global.add.v2.f32 [%0], {%1,%2};"
                         :: "l"(dst0), "f"(d0), "f"(d1) : "memory");
            float* dst1 = dst0 + 8 * BSTRIDE;
            asm volatile("red.global.add.v2.f32 [%0], {%1,%2};"
                         :: "l"(dst1), "f"(d2), "f"(d3) : "memory");
        }

        // R12-validated lockstep barrier
        if (t < T_ - 1) {
            __threadfence();       // order this thread's REDs gpu-wide
            __syncthreads();       // join ALL warps' REDs before tid0 arrives
            if (tid == 0) {
                unsigned target = (unsigned)t * NBLK;
                unsigned dummy;
                asm volatile("atom.release.gpu.global.add.u32 %0, [%1], %2;"
                             : "=r"(dummy) : "l"(&g_bar), "r"(1u) : "memory");
                unsigned v;
                do {
                    asm volatile("ld.acquire.gpu.global.u32 %0, [%1];"
                                 : "=r"(v) : "l"(&g_bar) : "memory");
                } while (v < target);
            }
            __syncthreads();       // broadcast barrier pass; guards smem reuse
        }
    }
}

// ---------------------------------------------------------------------------
extern "C" void kernel_launch(void* const* d_in, const int* in_sizes, int n_in,
                              void* d_out, int out_size) {
    (void)in_sizes; (void)n_in; (void)out_size;
    const float* x   = (const float*)d_in[0];
    const float* W   = (const float*)d_in[1];
    const float* Uw  = (const float*)d_in[2];
    const float* Ub  = (const float*)d_in[3];
    const float* bv  = (const float*)d_in[4];
    float* out = (float*)d_out;

    const int rnn_smem  = 4 * 64 * KP2 * 4;    // 135168 B
    const int proj_smem = 4 * 128 * PKP2 * 4;  // 73728 B
    cudaFuncSetAttribute(rnn_persistent_kernel,
                         cudaFuncAttributeMaxDynamicSharedMemorySize, rnn_smem);
    cudaFuncSetAttribute(proj_tf32_kernel,
                         cudaFuncAttributeMaxDynamicSharedMemorySize, proj_smem);

    init_kernel<<<1, 1>>>();
    proj_tf32_kernel<<<dim3(H_ / 128, MTOT / 128), 256, proj_smem>>>(
        x, W, Ub, bv, out);
    rnn_persistent_kernel<<<NBLK, 256, rnn_smem>>>(out, Uw);
}

// round 17
// speedup vs baseline: 1.6690x; 1.6690x over previous
#include <cuda_runtime.h>
#include <cuda_bf16.h>
#include <cstdint>

#define B_ 64
#define T_ 2048
#define I_ 512
#define H_ 1024
#define MTOT (B_ * T_)
#define BSTRIDE ((size_t)T_ * H_)   // stride between batch rows in out
#define NBLK 128                    // persistent grid: 16 n-tiles x 8 k-slabs
#define KP 136                      // rec padded k-row (128+8 bf16), conflict-free ldsm
#define ARR (64 * KP)
#define ARRB (ARR * 2)              // 17408 B per split plane
#define PKP2 36                     // proj padded k-row (32+4 fp32 words)

__device__ unsigned g_bar;          // grid-barrier arrival counter

// ---------------------------------------------------------------------------
// helpers
// ---------------------------------------------------------------------------
__device__ __forceinline__ unsigned smem_u32(const void* p) {
    return (unsigned)__cvta_generic_to_shared(p);
}
__device__ __forceinline__ void ldsm_x4(unsigned* r, unsigned addr) {
    asm volatile("ldmatrix.sync.aligned.m8n8.x4.shared.b16 {%0,%1,%2,%3}, [%4];"
                 : "=r"(r[0]), "=r"(r[1]), "=r"(r[2]), "=r"(r[3]) : "r"(addr));
}
__device__ __forceinline__ void mma_bf16(float* d, const unsigned* a, const unsigned* b) {
    asm volatile(
        "mma.sync.aligned.m16n8k16.row.col.f32.bf16.bf16.f32 "
        "{%0,%1,%2,%3}, {%4,%5,%6,%7}, {%8,%9}, {%0,%1,%2,%3};"
        : "+f"(d[0]), "+f"(d[1]), "+f"(d[2]), "+f"(d[3])
        : "r"(a[0]), "r"(a[1]), "r"(a[2]), "r"(a[3]), "r"(b[0]), "r"(b[1]));
}
__device__ __forceinline__ uint32_t f2tf32(float x) {
    uint32_t u;
    asm("cvt.rna.tf32.f32 %0, %1;" : "=r"(u) : "f"(x));
    return u;
}
__device__ __forceinline__ void mma_tf32(float* d, const uint32_t* a, const uint32_t* b) {
    asm volatile(
        "mma.sync.aligned.m16n8k8.row.col.f32.tf32.tf32.f32 "
        "{%0,%1,%2,%3}, {%4,%5,%6,%7}, {%8,%9}, {%0,%1,%2,%3};"
        : "+f"(d[0]), "+f"(d[1]), "+f"(d[2]), "+f"(d[3])
        : "r"(a[0]), "r"(a[1]), "r"(a[2]), "r"(a[3]), "r"(b[0]), "r"(b[1]));
}
// 2-way tf32 split (proj, R10-validated)
__device__ __forceinline__ void split4(float* hi, float* lo, float4 v) {
    float f[4] = {v.x, v.y, v.z, v.w};
    float h[4], l[4];
#pragma unroll
    for (int i = 0; i < 4; i++) {
        h[i] = __uint_as_float(f2tf32(f[i]));
        l[i] = __uint_as_float(f2tf32(f[i] - h[i]));
    }
    *(float4*)hi = make_float4(h[0], h[1], h[2], h[3]);
    *(float4*)lo = make_float4(l[0], l[1], l[2], l[3]);
}
// 3-way bf16 split: x = a + b + c (residual subtractions exact in fp32);
// packed 8B stores per plane.
__device__ __forceinline__ void cvt3(__nv_bfloat16* pa, __nv_bfloat16* pb,
                                     __nv_bfloat16* pc, float4 v) {
    float f[4] = {v.x, v.y, v.z, v.w};
    __nv_bfloat16 a[4], b[4], c[4];
#pragma unroll
    for (int i = 0; i < 4; i++) {
        a[i] = __float2bfloat16_rn(f[i]);
        float r = f[i] - __bfloat162float(a[i]);
        b[i] = __float2bfloat16_rn(r);
        float s = r - __bfloat162float(b[i]);
        c[i] = __float2bfloat16_rn(s);
    }
    __nv_bfloat162 a0 = __halves2bfloat162(a[0], a[1]), a1 = __halves2bfloat162(a[2], a[3]);
    __nv_bfloat162 b0 = __halves2bfloat162(b[0], b[1]), b1 = __halves2bfloat162(b[2], b[3]);
    __nv_bfloat162 c0 = __halves2bfloat162(c[0], c[1]), c1 = __halves2bfloat162(c[2], c[3]);
    *(uint2*)pa = make_uint2(*reinterpret_cast<unsigned*>(&a0), *reinterpret_cast<unsigned*>(&a1));
    *(uint2*)pb = make_uint2(*reinterpret_cast<unsigned*>(&b0), *reinterpret_cast<unsigned*>(&b1));
    *(uint2*)pc = make_uint2(*reinterpret_cast<unsigned*>(&c0), *reinterpret_cast<unsigned*>(&c1));
}

// ---------------------------------------------------------------------------
__global__ void init_kernel() { g_bar = 0u; }

// ---------------------------------------------------------------------------
// Projection (TF32 MMA, 2-way split, 4 terms) — R10-VALIDATED, byte-identical.
// ---------------------------------------------------------------------------
__global__ __launch_bounds__(256) void proj_tf32_kernel(
    const float* __restrict__ x, const float* __restrict__ W,
    const float* __restrict__ Ub, const float* __restrict__ bvec,
    float* __restrict__ out)
{
    extern __shared__ float psm[];
    float* Axh = psm;
    float* Axl = Axh + 128 * PKP2;
    float* Bwh = Axl + 128 * PKP2;
    float* Bwl = Bwh + 128 * PKP2;

    const int tid  = threadIdx.x;
    const int lane = tid & 31;
    const int g    = lane >> 2;
    const int tg   = lane & 3;
    const int wid  = tid >> 5;
    const int m0 = blockIdx.y * 128;
    const int n0 = blockIdx.x * 128;
    const int wm = (wid & 3) * 32;
    const int wn = (wid >> 2) * 64;

    float D[2][8][4];
#pragma unroll
    for (int i = 0; i < 2; i++)
#pragma unroll
        for (int j = 0; j < 8; j++)
#pragma unroll
            for (int k = 0; k < 4; k++) D[i][j][k] = 0.f;

    for (int kb = 0; kb < I_; kb += 32) {
        __syncthreads();
#pragma unroll
        for (int l = 0; l < 4; l++) {
            int idx = tid + l * 256;
            int row = idx >> 3;
            int c4  = (idx & 7) << 2;
            float4 xv = *(const float4*)(x + (size_t)(m0 + row) * I_ + kb + c4);
            split4(Axh + row * PKP2 + c4, Axl + row * PKP2 + c4, xv);
            float4 wv = *(const float4*)(W + (size_t)(n0 + row) * I_ + kb + c4);
            split4(Bwh + row * PKP2 + c4, Bwl + row * PKP2 + c4, wv);
        }
        __syncthreads();

#pragma unroll
        for (int kc = 0; kc < 4; kc++) {
            const int col = kc * 8 + tg;
            uint32_t ah[2][4], al[2][4];
#pragma unroll
            for (int mt = 0; mt < 2; mt++) {
                int r = wm + mt * 16 + g;
                ah[mt][0] = __float_as_uint(Axh[r * PKP2 + col]);
                ah[mt][1] = __float_as_uint(Axh[(r + 8) * PKP2 + col]);
                ah[mt][2] = __float_as_uint(Axh[r * PKP2 + col + 4]);
                ah[mt][3] = __float_as_uint(Axh[(r + 8) * PKP2 + col + 4]);
                al[mt][0] = __float_as_uint(Axl[r * PKP2 + col]);
                al[mt][1] = __float_as_uint(Axl[(r + 8) * PKP2 + col]);
                al[mt][2] = __float_as_uint(Axl[r * PKP2 + col + 4]);
                al[mt][3] = __float_as_uint(Axl[(r + 8) * PKP2 + col + 4]);
            }
#pragma unroll
            for (int nt = 0; nt < 8; nt++) {
                int n = wn + nt * 8 + g;
                uint32_t bh[2], bl[2];
                bh[0] = __float_as_uint(Bwh[n * PKP2 + col]);
                bh[1] = __float_as_uint(Bwh[n * PKP2 + col + 4]);
                bl[0] = __float_as_uint(Bwl[n * PKP2 + col]);
                bl[1] = __float_as_uint(Bwl[n * PKP2 + col + 4]);
#pragma unroll
                for (int mt = 0; mt < 2; mt++) {
                    mma_tf32(D[mt][nt], ah[mt], bh);
                    mma_tf32(D[mt][nt], ah[mt], bl);
                    mma_tf32(D[mt][nt], al[mt], bh);
                    mma_tf32(D[mt][nt], al[mt], bl);
                }
            }
        }
    }

#pragma unroll
    for (int nt = 0; nt < 8; nt++) {
        int n = n0 + wn + nt * 8 + tg * 2;
        float ub0 = Ub[n]     + bvec[n];
        float ub1 = Ub[n + 1] + bvec[n + 1];
#pragma unroll
        for (int mt = 0; mt < 2; mt++) {
            int m = m0 + wm + mt * 16 + g;
            float2 v0 = make_float2(D[mt][nt][0] + ub0, D[mt][nt][1] + ub1);
            float2 v1 = make_float2(D[mt][nt][2] + ub0, D[mt][nt][3] + ub1);
            *(float2*)(out + (size_t)m * H_ + n)       = v0;
            *(float2*)(out + (size_t)(m + 8) * H_ + n) = v1;
        }
    }
}

// ---------------------------------------------------------------------------
// Persistent recurrence — bf16 3-way split, 6 terms (aa ab ba bb ac ca),
// SHORT CHAINS on the dominant aa term (length 2, RN FADD combine) to kill the
// MMA-accumulator truncation bias (R16-validated mechanism). Small terms
// (<=2^-9 magnitude) stay in one long chain (bias scaled down ~500x).
//   out[b][t][n] += sum_k out[b][t-1][k] * Uw[n][k]
// Fragment layout byte-identical to R6 (error there was exactly bias-level =>
// layout correct). R12-validated lockstep barrier.
// ---------------------------------------------------------------------------
__global__ __launch_bounds__(256) void rnn_persistent_kernel(
    float* __restrict__ out, const float* __restrict__ Uw)
{
    extern __shared__ __nv_bfloat16 sm[];
    __nv_bfloat16* Ua  = sm;                 // [64][KP] each
    __nv_bfloat16* Ub2 = Ua + ARR;
    __nv_bfloat16* Uc  = Ub2 + ARR;
    __nv_bfloat16* Sa  = Uc + ARR;
    __nv_bfloat16* Sb  = Sa + ARR;
    __nv_bfloat16* Sc  = Sb + ARR;
    const unsigned OFF = ARRB;

    const int tid  = threadIdx.x;
    const int lane = tid & 31;
    const int wid  = tid >> 5;
    const int bid  = blockIdx.x;
    const int n0 = (bid & 15) * 64;
    const int k0 = (bid >> 4) * 128;
    const int wm = (wid & 3) * 16;    // batch-row tile (16 of 64)
    const int wn = (wid >> 2) * 32;   // n offset within 64 (2 halves)

    // Preload Uw slab once: rows n (64), cols k (128), 3-way split
#pragma unroll
    for (int l = 0; l < 8; l++) {
        int idx = tid + l * 256;     // 0..2047
        int r   = idx >> 5;          // 0..63  (n)
        int c4  = (idx & 31) << 2;   // 0..124 (k)
        float4 v = *(const float4*)(Uw + (size_t)(n0 + r) * H_ + k0 + c4);
        cvt3(Ua + r * KP + c4, Ub2 + r * KP + c4, Uc + r * KP + c4, v);
    }
    __syncthreads();

    for (int t = 1; t < T_; t++) {
        // Stage prev state slab [64 b][128 k] fp32 -> 3-way bf16
        const float* prev = out + (size_t)(t - 1) * H_ + k0;
#pragma unroll
        for (int l = 0; l < 8; l++) {
            int idx = tid + l * 256;
            int r   = idx >> 5;          // batch row
            int c4  = (idx & 31) << 2;
            float4 v = *(const float4*)(prev + (size_t)r * BSTRIDE + c4);
            cvt3(Sa + r * KP + c4, Sb + r * KP + c4, Sc + r * KP + c4, v);
        }
        __syncthreads();

        float Dsum[4][4], Daa[4][4], Drest[4][4];
#pragma unroll
        for (int i = 0; i < 4; i++)
#pragma unroll
            for (int j = 0; j < 4; j++) { Dsum[i][j] = 0.f; Drest[i][j] = 0.f; }

#pragma unroll
        for (int ks = 0; ks < 8; ks++) {
            unsigned Fa[4], Fb[4], Fc[4];
            unsigned aaddr = smem_u32(Sa + (wm + (lane & 15)) * KP
                                         + ks * 16 + (lane >> 4) * 8);
            ldsm_x4(Fa, aaddr);
            ldsm_x4(Fb, aaddr + OFF);
            ldsm_x4(Fc, aaddr + 2 * OFF);

            if ((ks & 1) == 0) {   // open fresh length-2 aa chains
#pragma unroll
                for (int i = 0; i < 4; i++)
#pragma unroll
                    for (int j = 0; j < 4; j++) Daa[i][j] = 0.f;
            }

#pragma unroll
            for (int ntp = 0; ntp < 2; ntp++) {
                unsigned Ga[4], Gb[4], Gc[4];
                unsigned baddr = smem_u32(
                    Ua + (wn + ntp * 16 + ((lane >> 4) & 1) * 8 + (lane & 7)) * KP
                       + ks * 16 + ((lane >> 3) & 1) * 8);
                ldsm_x4(Ga, baddr);
                ldsm_x4(Gb, baddr + OFF);
                ldsm_x4(Gc, baddr + 2 * OFF);
#pragma unroll
                for (int h = 0; h < 2; h++) {
                    int di = 2 * ntp + h;
                    mma_bf16(Daa[di],   Fa, Ga + 2 * h);   // aa  (short chain)
                    mma_bf16(Drest[di], Fa, Gb + 2 * h);   // ab  (long chain, ~2^-9)
                    mma_bf16(Drest[di], Fb, Ga + 2 * h);   // ba
                    mma_bf16(Drest[di], Fb, Gb + 2 * h);   // bb
                    mma_bf16(Drest[di], Fa, Gc + 2 * h);   // ac
                    mma_bf16(Drest[di], Fc, Ga + 2 * h);   // ca
                }
            }

            if ((ks & 1) == 1) {   // close aa chains: RN-add into Dsum
#pragma unroll
                for (int i = 0; i < 4; i++)
#pragma unroll
                    for (int j = 0; j < 4; j++) Dsum[i][j] += Daa[i][j];
            }
        }

        // Merge partials onto wx at out[:, t, :]
#pragma unroll
        for (int nt = 0; nt < 4; nt++) {
            float d0 = Dsum[nt][0] + Drest[nt][0];
            float d1 = Dsum[nt][1] + Drest[nt][1];
            float d2 = Dsum[nt][2] + Drest[nt][2];
            float d3 = Dsum[nt][3] + Drest[nt][3];
            int n  = n0 + wn + nt * 8 + (lane & 3) * 2;
            int br = wm + (lane >> 2);
            float* dst0 = out + (size_t)br * BSTRIDE + (size_t)t * H_ + n;
            asm volatile("red.global.add.v2.f32 [%0], {%1,%2};"
                         :: "l"(dst0), "f"(d0), "f"(d1) : "memory");
            float* dst1 = dst0 + 8 * BSTRIDE;
            asm volatile("red.global.add.v2.f32 [%0], {%1,%2};"
                         :: "l"(dst1), "f"(d2), "f"(d3) : "memory");
        }

        // R12-validated lockstep barrier
        if (t < T_ - 1) {
            __threadfence();
            __syncthreads();
            if (tid == 0) {
                unsigned target = (unsigned)t * NBLK;
                atomicAdd(&g_bar, 1u);
                unsigned v;
                do {
                    asm volatile("ld.acquire.gpu.global.u32 %0, [%1];"
                                 : "=r"(v) : "l"(&g_bar));
                } while (v < target);
            }
            __syncthreads();
        }
    }
}

// ---------------------------------------------------------------------------
extern "C" void kernel_launch(void* const* d_in, const int* in_sizes, int n_in,
                              void* d_out, int out_size) {
    (void)in_sizes; (void)n_in; (void)out_size;
    const float* x   = (const float*)d_in[0];
    const float* W   = (const float*)d_in[1];
    const float* Uw  = (const float*)d_in[2];
    const float* Ub  = (const float*)d_in[3];
    const float* bv  = (const float*)d_in[4];
    float* out = (float*)d_out;

    const int rnn_smem  = 6 * ARRB;            // 104448 B
    const int proj_smem = 4 * 128 * PKP2 * 4;  // 73728 B
    cudaFuncSetAttribute(rnn_persistent_kernel,
                         cudaFuncAttributeMaxDynamicSharedMemorySize, rnn_smem);
    cudaFuncSetAttribute(proj_tf32_kernel,
                         cudaFuncAttributeMaxDynamicSharedMemorySize, proj_smem);

    init_kernel<<<1, 1>>>();
    proj_tf32_kernel<<<dim3(H_ / 128, MTOT / 128), 256, proj_smem>>>(
        x, W, Ub, bv, out);
    rnn_persistent_kernel<<<NBLK, 256, rnn_smem>>>(out, Uw);
}